// round 3
// baseline (speedup 1.0000x reference)
#include <cuda_runtime.h>
#include <math.h>

// Qwen2.5 MoE expert router, fused: GEMM(logits) + softmax + top-2 + dispatch + aux loss.
// x: [N, D] fp32, w_router: [E, D] fp32.
// out (fp32, concatenated in reference return order):
//   [0          , N*E)        dispatch_tensor
//   [N*E        , 2*N*E)      combine_tensor (== dispatch)
//   [2*N*E      , 3*N*E)      router_logits
//   [3*N*E      , 4*N*E)      router_probs
//   [4*N*E]                   aux_loss
//   [4*N*E+1    , 4*N*E+1+2N) top_k_indices (as float)
//   [4*N*E+1+2N , 4*N*E+1+4N) top_k_probs_norm

#define D_DIM 2048
#define E_DIM 64
#define BM 128
#define BK 32
#define NTHREADS 256
#define TM 8
#define TN 4
#define KT (D_DIM / BK)       // 64 k-tiles
#define A_STRIDE (BM + 4)     // 132: transposed-store + float4-read conflict free
#define B_STRIDE (E_DIM + 4)  // 68
#define L_STRIDE (E_DIM + 1)  // 65

#define A_ELEMS (BK * A_STRIDE)            // 4224
#define B_ELEMS (BK * B_STRIDE)            // 2176
#define L_ELEMS (BM * L_STRIDE)            // 8320
#define SPART_ELEMS (8 * E_DIM)            // 512
#define SMEM_ELEMS (L_ELEMS + SPART_ELEMS) // 8832 floats (> A+B = 6400)

// per-block per-expert prob sums (deterministic two-stage aux reduction)
__device__ float g_partials[512 * E_DIM];

__global__ __launch_bounds__(NTHREADS)
void router_fused_kernel(const float* __restrict__ x,
                         const float* __restrict__ w,
                         float* __restrict__ out,
                         int N)
{
    __shared__ float smem[SMEM_ELEMS];
    float* As = smem;                // [BK][BM+4], GEMM phase
    float* Bs = smem + A_ELEMS;      // [BK][E+4],  GEMM phase
    float* Lg = smem;                // [BM][E+1],  epilogue phase (aliases As/Bs)
    float* sPart = smem + L_ELEMS;   // [8][E],     epilogue phase

    const int tid = threadIdx.x;
    const int block_row = blockIdx.x * BM;

    const int tx = tid & 15;       // expert group 0..15
    const int ty = tid >> 4;       // token group 0..15
    const int e0 = tx * TN;        // 0,4,...,60
    const int m0 = ty * TM;        // 0,8,...,120

    // global->smem load mapping: lane k-offset and row within tile
    const int lk = (tid & 7) * 4;  // 0..28
    const int lr = tid >> 3;       // 0..31

    float4 aReg[4];
    float4 bReg[2];

    float acc[TM][TN];
    #pragma unroll
    for (int i = 0; i < TM; i++)
        #pragma unroll
        for (int j = 0; j < TN; j++) acc[i][j] = 0.f;

    // ---- prologue: stage tile 0 into registers ----
    {
        const int kbase = 0;
        #pragma unroll
        for (int p = 0; p < 4; p++) {
            int row = block_row + p * 32 + lr;
            if (row < N)
                aReg[p] = *reinterpret_cast<const float4*>(x + (size_t)row * D_DIM + kbase + lk);
            else
                aReg[p] = make_float4(0.f, 0.f, 0.f, 0.f);
        }
        #pragma unroll
        for (int p = 0; p < 2; p++) {
            int erow = p * 32 + lr;
            bReg[p] = *reinterpret_cast<const float4*>(w + (size_t)erow * D_DIM + kbase + lk);
        }
    }

    // ---- main loop: store staged tile, prefetch next, compute ----
    for (int kt = 0; kt < KT; kt++) {
        __syncthreads();  // previous compute done reading smem

        #pragma unroll
        for (int p = 0; p < 4; p++) {
            int m = p * 32 + lr;
            As[(lk + 0) * A_STRIDE + m] = aReg[p].x;
            As[(lk + 1) * A_STRIDE + m] = aReg[p].y;
            As[(lk + 2) * A_STRIDE + m] = aReg[p].z;
            As[(lk + 3) * A_STRIDE + m] = aReg[p].w;
        }
        #pragma unroll
        for (int p = 0; p < 2; p++) {
            int e = p * 32 + lr;
            Bs[(lk + 0) * B_STRIDE + e] = bReg[p].x;
            Bs[(lk + 1) * B_STRIDE + e] = bReg[p].y;
            Bs[(lk + 2) * B_STRIDE + e] = bReg[p].z;
            Bs[(lk + 3) * B_STRIDE + e] = bReg[p].w;
        }
        __syncthreads();

        if (kt + 1 < KT) {
            const int kbase = (kt + 1) * BK;
            #pragma unroll
            for (int p = 0; p < 4; p++) {
                int row = block_row + p * 32 + lr;
                if (row < N)
                    aReg[p] = *reinterpret_cast<const float4*>(x + (size_t)row * D_DIM + kbase + lk);
                else
                    aReg[p] = make_float4(0.f, 0.f, 0.f, 0.f);
            }
            #pragma unroll
            for (int p = 0; p < 2; p++) {
                int erow = p * 32 + lr;
                bReg[p] = *reinterpret_cast<const float4*>(w + (size_t)erow * D_DIM + kbase + lk);
            }
        }

        #pragma unroll 8
        for (int kk = 0; kk < BK; kk++) {
            float4 a0 = *reinterpret_cast<const float4*>(&As[kk * A_STRIDE + m0]);
            float4 a1 = *reinterpret_cast<const float4*>(&As[kk * A_STRIDE + m0 + 4]);
            float4 b  = *reinterpret_cast<const float4*>(&Bs[kk * B_STRIDE + e0]);
            float av[TM] = {a0.x, a0.y, a0.z, a0.w, a1.x, a1.y, a1.z, a1.w};
            float bv[TN] = {b.x, b.y, b.z, b.w};
            #pragma unroll
            for (int i = 0; i < TM; i++)
                #pragma unroll
                for (int j = 0; j < TN; j++)
                    acc[i][j] = fmaf(av[i], bv[j], acc[i][j]);
        }
    }

    // ---- epilogue: logits -> smem, per-token softmax/top-2/scatter ----
    __syncthreads();  // done with As/Bs; reuse as Lg
    #pragma unroll
    for (int i = 0; i < TM; i++)
        #pragma unroll
        for (int j = 0; j < TN; j++)
            Lg[(m0 + i) * L_STRIDE + (e0 + j)] = acc[i][j];
    for (int s = tid; s < SPART_ELEMS; s += NTHREADS) sPart[s] = 0.f;
    __syncthreads();

    const int warpId = tid >> 5;
    const int lane = tid & 31;
    const size_t NE = (size_t)N * E_DIM;
    const float NEG_INF = __int_as_float(0xff800000);

    float auxA = 0.f, auxB = 0.f;  // prob sums for experts (lane) and (lane+32)

    for (int tk = warpId; tk < BM; tk += 8) {
        int n = block_row + tk;
        if (n >= N) continue;  // warp-uniform

        float v0 = Lg[tk * L_STRIDE + lane];
        float v1 = Lg[tk * L_STRIDE + lane + 32];

        // softmax over 64 experts (2 per lane)
        float mx = fmaxf(v0, v1);
        #pragma unroll
        for (int o = 16; o; o >>= 1) mx = fmaxf(mx, __shfl_xor_sync(0xffffffffu, mx, o));
        float x0 = expf(v0 - mx), x1 = expf(v1 - mx);
        float s = x0 + x1;
        #pragma unroll
        for (int o = 16; o; o >>= 1) s += __shfl_xor_sync(0xffffffffu, s, o);
        float p0 = x0 / s, p1 = x1 / s;
        auxA += p0; auxB += p1;

        // top-1 (tie -> smallest index, matching jax.lax.top_k)
        float bvv; int bi;
        if (p0 >= p1) { bvv = p0; bi = lane; } else { bvv = p1; bi = lane + 32; }
        #pragma unroll
        for (int o = 16; o; o >>= 1) {
            float ov = __shfl_xor_sync(0xffffffffu, bvv, o);
            int   oi = __shfl_xor_sync(0xffffffffu, bi, o);
            if (ov > bvv || (ov == bvv && oi < bi)) { bvv = ov; bi = oi; }
        }
        // top-2: exclude top-1 index
        float c0 = (lane == bi) ? NEG_INF : p0;
        float c1 = (lane + 32 == bi) ? NEG_INF : p1;
        float sv; int si;
        if (c0 >= c1) { sv = c0; si = lane; } else { sv = c1; si = lane + 32; }
        #pragma unroll
        for (int o = 16; o; o >>= 1) {
            float ov = __shfl_xor_sync(0xffffffffu, sv, o);
            int   oi = __shfl_xor_sync(0xffffffffu, si, o);
            if (ov > sv || (ov == sv && oi < si)) { sv = ov; si = oi; }
        }

        float tsum = bvv + sv;
        float pn1 = bvv / tsum, pn2 = sv / tsum;

        size_t rowL = (size_t)n * E_DIM;
        // logits, probs
        out[2 * NE + rowL + lane]      = v0;
        out[2 * NE + rowL + lane + 32] = v1;
        out[3 * NE + rowL + lane]      = p0;
        out[3 * NE + rowL + lane + 32] = p1;
        // dispatch == combine
        float d0 = (lane == bi) ? pn1 : ((lane == si) ? pn2 : 0.f);
        float d1 = (lane + 32 == bi) ? pn1 : ((lane + 32 == si) ? pn2 : 0.f);
        out[rowL + lane]           = d0;
        out[rowL + lane + 32]      = d1;
        out[NE + rowL + lane]      = d0;
        out[NE + rowL + lane + 32] = d1;
        if (lane == 0) {
            size_t o5 = 4 * NE + 1 + (size_t)n * 2;
            out[o5]     = (float)bi;
            out[o5 + 1] = (float)si;
            size_t o6 = 4 * NE + 1 + (size_t)N * 2 + (size_t)n * 2;
            out[o6]     = pn1;
            out[o6 + 1] = pn2;
        }
    }

    // per-block per-expert prob sums (deterministic: each warp owns its row)
    sPart[warpId * E_DIM + lane]      = auxA;
    sPart[warpId * E_DIM + lane + 32] = auxB;
    __syncthreads();
    if (tid < E_DIM) {
        float ssum = 0.f;
        #pragma unroll
        for (int wd = 0; wd < 8; wd++) ssum += sPart[wd * E_DIM + tid];
        g_partials[blockIdx.x * E_DIM + tid] = ssum;
    }
}

__global__ void aux_loss_kernel(float* __restrict__ out, int N, int nBlocks)
{
    __shared__ float sm[E_DIM];
    int e = threadIdx.x;  // 64 threads
    float s = 0.f;
    for (int b = 0; b < nBlocks; b++) s += g_partials[b * E_DIM + e];
    float m = s / (float)N;
    sm[e] = m * m;
    __syncthreads();
    if (e == 0) {
        float a = 0.f;
        #pragma unroll
        for (int i = 0; i < E_DIM; i++) a += sm[i];
        // aux_loss = mean_e(E * pbar^2) = sum_e pbar^2
        out[(size_t)4 * N * E_DIM] = a;
    }
}

extern "C" void kernel_launch(void* const* d_in, const int* in_sizes, int n_in,
                              void* d_out, int out_size)
{
    const float* x = (const float*)d_in[0];       // [N, 2048]
    const float* w = (const float*)d_in[1];       // [64, 2048]
    float* out = (float*)d_out;

    int N = in_sizes[0] / D_DIM;                  // 16384
    int nBlocks = (N + BM - 1) / BM;              // 128

    router_fused_kernel<<<nBlocks, NTHREADS>>>(x, w, out, N);
    aux_loss_kernel<<<1, E_DIM>>>(out, N, nBlocks);
}